// round 1
// baseline (speedup 1.0000x reference)
#include <cuda_runtime.h>
#include <math.h>
#include <stdint.h>

// Problem constants
#define NN   25600          // nodes
#define EE   409600         // edges
#define GG   128            // graphs
#define INF_ 200            // raw feature dim
#define IN2  400            // 2*IN after nan-mask concat
#define HC4  256            // H*C for layers 0/1
#define ETOT (EE + NN)      // edges + self loops

// ---------------- scratch (device globals; no allocation allowed) ----------------
__device__ __align__(16) float d_xcat[(size_t)NN * IN2];     // 41 MB
__device__ __align__(16) float d_h   [(size_t)NN * HC4];     // 26 MB  (GEMM output / attn input)
__device__ __align__(16) float d_xn  [(size_t)NN * HC4];     // 26 MB  (next-layer input)
__device__ __align__(16) float d_o2  [(size_t)NN * 64];      // layer-2 node output
__device__ float d_asb[NN * 4];
__device__ float d_adb[NN * 4];
__device__ int   d_cnt[NN];
__device__ int   d_fill[NN];
__device__ float d_easum[NN];
__device__ int   d_rowptr[NN + 1];
__device__ int   d_csrc[ETOT];
__device__ float d_cea [ETOT];
__device__ float d_gsum[GG * 64];
__device__ float d_gcnt[GG];
__device__ float d_wd[9];   // we_dot: layer0 heads 0..3, layer1 heads 4..7, layer2 at 8

// ---------------- helpers ----------------
__device__ __forceinline__ float warp_max(float v) {
    #pragma unroll
    for (int o = 16; o; o >>= 1) v = fmaxf(v, __shfl_xor_sync(0xffffffffu, v, o));
    return v;
}
__device__ __forceinline__ float warp_sum(float v) {
    #pragma unroll
    for (int o = 16; o; o >>= 1) v += __shfl_xor_sync(0xffffffffu, v, o);
    return v;
}

// ---------------- zero scratch counters ----------------
__global__ void zero_kernel() {
    int i = blockIdx.x * blockDim.x + threadIdx.x;
    if (i < NN) { d_cnt[i] = 0; d_fill[i] = 0; d_easum[i] = 0.f; }
    if (i < GG * 64) d_gsum[i] = 0.f;
    if (i < GG) d_gcnt[i] = 0.f;
}

// ---------------- CSR build ----------------
__global__ void count_kernel(const int* __restrict__ ei, const float* __restrict__ ea) {
    int e = blockIdx.x * blockDim.x + threadIdx.x;
    if (e >= EE) return;
    int d = ei[EE + e];
    float v = ea[e];
    if (v != v) v = 0.f;              // nan_to_num
    atomicAdd(&d_cnt[d], 1);
    atomicAdd(&d_easum[d], v);
}

// single-block exclusive scan of (cnt[n]+1) -> rowptr.  25600 = 25 * 1024 exactly.
__global__ void scan_kernel() {
    __shared__ int sdata[1024];
    __shared__ int s_off;
    int tid = threadIdx.x;
    if (tid == 0) { d_rowptr[0] = 0; s_off = 0; }
    __syncthreads();
    for (int base = 0; base < NN; base += 1024) {
        int v = d_cnt[base + tid] + 1;    // +1 for the self loop
        sdata[tid] = v;
        __syncthreads();
        for (int off = 1; off < 1024; off <<= 1) {
            int t = (tid >= off) ? sdata[tid - off] : 0;
            __syncthreads();
            sdata[tid] += t;
            __syncthreads();
        }
        d_rowptr[base + tid + 1] = s_off + sdata[tid];
        __syncthreads();
        if (tid == 0) s_off += sdata[1023];
        __syncthreads();
    }
}

__global__ void fill_kernel(const int* __restrict__ ei, const float* __restrict__ ea) {
    int e = blockIdx.x * blockDim.x + threadIdx.x;
    if (e >= EE) return;
    int s = ei[e], d = ei[EE + e];
    float v = ea[e];
    if (v != v) v = 0.f;
    int pos = d_rowptr[d] + atomicAdd(&d_fill[d], 1);
    d_csrc[pos] = s;
    d_cea[pos]  = v;
}

__global__ void selfloop_kernel() {
    int n = blockIdx.x * blockDim.x + threadIdx.x;
    if (n >= NN) return;
    int pos = d_rowptr[n + 1] - 1;    // self loop occupies the last slot of the row
    d_csrc[pos] = n;
    d_cea[pos]  = d_easum[n] / fmaxf((float)d_cnt[n], 1.f);
}

// ---------------- feature prep: [nan_to_num(x), isnan(x)] ----------------
__global__ void xcat_kernel(const float* __restrict__ x) {
    int i = blockIdx.x * blockDim.x + threadIdx.x;
    if (i >= NN * INF_) return;
    int n = i / INF_, k = i % INF_;
    float v = x[i];
    bool isn = (v != v);
    d_xcat[(size_t)n * IN2 + k]        = isn ? 0.f : v;
    d_xcat[(size_t)n * IN2 + INF_ + k] = isn ? 1.f : 0.f;
}

// ---------------- we_dot[h] = dot(We row of head h, ae[h]) ----------------
__global__ void wd_kernel(const float* We0, const float* ae0,
                          const float* We1, const float* ae1,
                          const float* We2, const float* ae2) {
    int w = threadIdx.x >> 5, lane = threadIdx.x & 31;
    if (w >= 9) return;
    const float *We, *ae; int h;
    if (w < 4)      { We = We0; ae = ae0; h = w; }
    else if (w < 8) { We = We1; ae = ae1; h = w - 4; }
    else            { We = We2; ae = ae2; h = 0; }
    float s = 0.f;
    for (int c = lane; c < 64; c += 32) s += We[h * 64 + c] * ae[h * 64 + c];
    s = warp_sum(s);
    if (lane == 0) d_wd[w] = s;
}

// ---------------- tiled fp32 GEMM: d_h = A @ B, A row-major [25600,K], B [K,Nn] ----------------
__global__ void gemm_kernel(int asel, const float* __restrict__ B, int Nn, int K) {
    const float* A = asel ? d_xn : d_xcat;
    __shared__ __align__(16) float As[16][64];
    __shared__ __align__(16) float Bs[16][64];
    int tid = threadIdx.x;              // 256 threads
    int tx = tid & 15, ty = tid >> 4;   // 16x16, each thread 4x4
    int m0 = blockIdx.y << 6, n0 = blockIdx.x << 6;
    float acc[4][4] = {};
    for (int k0 = 0; k0 < K; k0 += 16) {
        #pragma unroll
        for (int r = 0; r < 4; r++) {
            int el = tid + (r << 8);
            As[el & 15][el >> 4] = A[(size_t)(m0 + (el >> 4)) * K + k0 + (el & 15)];
            Bs[el >> 6][el & 63] = B[(size_t)(k0 + (el >> 6)) * Nn + n0 + (el & 63)];
        }
        __syncthreads();
        #pragma unroll
        for (int k = 0; k < 16; k++) {
            float4 av = *(const float4*)&As[k][ty << 2];
            float4 bv = *(const float4*)&Bs[k][tx << 2];
            float a[4] = {av.x, av.y, av.z, av.w};
            float b[4] = {bv.x, bv.y, bv.z, bv.w};
            #pragma unroll
            for (int i = 0; i < 4; i++)
                #pragma unroll
                for (int j = 0; j < 4; j++) acc[i][j] = fmaf(a[i], b[j], acc[i][j]);
        }
        __syncthreads();
    }
    #pragma unroll
    for (int i = 0; i < 4; i++)
        #pragma unroll
        for (int j = 0; j < 4; j++)
            d_h[(size_t)(m0 + (ty << 2) + i) * Nn + n0 + (tx << 2) + j] = acc[i][j];
}

// ---------------- per-node attention scalars a_s, a_d ----------------
__global__ void attn_kernel(int Hh, const float* __restrict__ att_s, const float* __restrict__ att_d) {
    int n = blockIdx.x;
    int w = threadIdx.x >> 5, lane = threadIdx.x & 31;
    const float* hr = d_h + (size_t)n * Hh * 64 + w * 64;
    float s = 0.f, dd = 0.f;
    for (int c = lane; c < 64; c += 32) {
        float hv = hr[c];
        s  += hv * att_s[w * 64 + c];
        dd += hv * att_d[w * 64 + c];
    }
    s = warp_sum(s); dd = warp_sum(dd);
    if (lane == 0) { d_asb[n * Hh + w] = s; d_adb[n * Hh + w] = dd; }
}

// ---------------- segment softmax + aggregation: one warp per dst node ----------------
template <int H>
__global__ void agg_kernel(const float* __restrict__ bias,
                           const float* __restrict__ bng, const float* __restrict__ bnb,
                           const float* __restrict__ bnm, const float* __restrict__ bnv,
                           int wd_off, int do_bn, int out_sel) {
    int gw = (blockIdx.x * blockDim.x + threadIdx.x) >> 5;
    if (gw >= NN) return;
    int lane = threadIdx.x & 31;
    int n = gw;
    int beg = d_rowptr[n], end = d_rowptr[n + 1];

    float adh[H], wdv[H];
    #pragma unroll
    for (int h = 0; h < H; h++) { adh[h] = d_adb[n * H + h]; wdv[h] = d_wd[wd_off + h]; }

    // pass 1: segment max per head
    float mx[H];
    #pragma unroll
    for (int h = 0; h < H; h++) mx[h] = -INFINITY;
    for (int e = beg + lane; e < end; e += 32) {
        int s = d_csrc[e]; float ev = d_cea[e];
        #pragma unroll
        for (int h = 0; h < H; h++) {
            float t = d_asb[s * H + h] + adh[h] + ev * wdv[h];
            t = t > 0.f ? t : 0.2f * t;
            mx[h] = fmaxf(mx[h], t);
        }
    }
    #pragma unroll
    for (int h = 0; h < H; h++) mx[h] = warp_max(mx[h]);

    // pass 2: segment sum of exp
    float sm[H];
    #pragma unroll
    for (int h = 0; h < H; h++) sm[h] = 0.f;
    for (int e = beg + lane; e < end; e += 32) {
        int s = d_csrc[e]; float ev = d_cea[e];
        #pragma unroll
        for (int h = 0; h < H; h++) {
            float t = d_asb[s * H + h] + adh[h] + ev * wdv[h];
            t = t > 0.f ? t : 0.2f * t;
            sm[h] += expf(t - mx[h]);
        }
    }
    #pragma unroll
    for (int h = 0; h < H; h++) sm[h] = warp_sum(sm[h]);

    // pass 3: weighted aggregation; each lane owns PL consecutive channels
    constexpr int PL = (H * 64) / 32;     // 8 (H=4) or 2 (H=1)
    int hl = (lane * PL) >> 6;            // head of this lane's channels
    float adl = adh[hl], wdl = wdv[hl], mxl = mx[hl];
    float invl = 1.f / (sm[hl] + 1e-16f);
    float acc[PL];
    #pragma unroll
    for (int j = 0; j < PL; j++) acc[j] = 0.f;

    for (int e = beg; e < end; e++) {
        int s = d_csrc[e]; float ev = d_cea[e];
        float t = d_asb[s * H + hl] + adl + ev * wdl;
        t = t > 0.f ? t : 0.2f * t;
        float w = expf(t - mxl) * invl;
        const float* hr = d_h + (size_t)s * (H * 64) + lane * PL;
        if constexpr (PL == 8) {
            float4 v0 = *(const float4*)hr;
            float4 v1 = *(const float4*)(hr + 4);
            acc[0] = fmaf(w, v0.x, acc[0]); acc[1] = fmaf(w, v0.y, acc[1]);
            acc[2] = fmaf(w, v0.z, acc[2]); acc[3] = fmaf(w, v0.w, acc[3]);
            acc[4] = fmaf(w, v1.x, acc[4]); acc[5] = fmaf(w, v1.y, acc[5]);
            acc[6] = fmaf(w, v1.z, acc[6]); acc[7] = fmaf(w, v1.w, acc[7]);
        } else {
            float2 v = *(const float2*)hr;
            acc[0] = fmaf(w, v.x, acc[0]);
            acc[1] = fmaf(w, v.y, acc[1]);
        }
    }

    float* ob = out_sel ? d_o2 : d_xn;
    #pragma unroll
    for (int j = 0; j < PL; j++) {
        int c = lane * PL + j;
        float v = acc[j] + bias[c];
        if (do_bn) {
            v = (v - bnm[c]) * rsqrtf(bnv[c] + 1e-5f) * bng[c] + bnb[c];
            v = fmaxf(v, 0.f);
        }
        ob[(size_t)n * (H * 64) + c] = v;
    }
}

// ---------------- global mean pool accumulation ----------------
__global__ void pool_kernel(const int* __restrict__ batch) {
    int n = blockIdx.x; int c = threadIdx.x;   // 64 threads
    int b = batch[n];
    atomicAdd(&d_gsum[b * 64 + c], d_o2[(size_t)n * 64 + c]);
    if (c == 0) atomicAdd(&d_gcnt[b], 1.f);
}

// ---------------- MLP head: GELU(g@cw1+cb1)@cw2+cb2 ----------------
__global__ void head_kernel(const float* __restrict__ cw1, const float* __restrict__ cb1,
                            const float* __restrict__ cw2, const float* __restrict__ cb2,
                            float* __restrict__ out) {
    int g = blockIdx.x, j = threadIdx.x;   // 64 threads
    __shared__ float sg[64], sh[64];
    float cntv = fmaxf(d_gcnt[g], 1.f);
    sg[j] = d_gsum[g * 64 + j] / cntv;
    __syncthreads();
    float a = cb1[j];
    #pragma unroll
    for (int k = 0; k < 64; k++) a = fmaf(sg[k], cw1[k * 64 + j], a);
    sh[j] = 0.5f * a * (1.f + erff(a * 0.70710678118654752440f));   // exact GELU
    __syncthreads();
    if (j < 2) {
        float o = cb2[j];
        #pragma unroll
        for (int k = 0; k < 64; k++) o = fmaf(sh[k], cw2[k * 2 + j], o);
        out[g * 2 + j] = o;
    }
}

// ---------------- launch ----------------
extern "C" void kernel_launch(void* const* d_in, const int* in_sizes, int n_in,
                              void* d_out, int out_size) {
    (void)in_sizes; (void)n_in; (void)out_size;
    const float* x     = (const float*)d_in[0];
    const int*   ei    = (const int*)  d_in[1];
    const float* ea    = (const float*)d_in[2];
    const int*   batch = (const int*)  d_in[3];
    const float* W0  = (const float*)d_in[4];
    const float* as0 = (const float*)d_in[5];
    const float* ad0 = (const float*)d_in[6];
    const float* We0 = (const float*)d_in[7];
    const float* ae0 = (const float*)d_in[8];
    const float* b0  = (const float*)d_in[9];
    const float* W1  = (const float*)d_in[10];
    const float* as1 = (const float*)d_in[11];
    const float* ad1 = (const float*)d_in[12];
    const float* We1 = (const float*)d_in[13];
    const float* ae1 = (const float*)d_in[14];
    const float* b1  = (const float*)d_in[15];
    const float* W2  = (const float*)d_in[16];
    const float* as2 = (const float*)d_in[17];
    const float* ad2 = (const float*)d_in[18];
    const float* We2 = (const float*)d_in[19];
    const float* ae2 = (const float*)d_in[20];
    const float* b2  = (const float*)d_in[21];
    const float* bng = (const float*)d_in[22];
    const float* bnb = (const float*)d_in[23];
    const float* bnm = (const float*)d_in[24];
    const float* bnv = (const float*)d_in[25];
    const float* cw1 = (const float*)d_in[26];
    const float* cb1 = (const float*)d_in[27];
    const float* cw2 = (const float*)d_in[28];
    const float* cb2 = (const float*)d_in[29];
    float* out = (float*)d_out;

    // graph prep (identical across layers)
    zero_kernel<<<100, 256>>>();
    count_kernel<<<EE / 256, 256>>>(ei, ea);
    scan_kernel<<<1, 1024>>>();
    fill_kernel<<<EE / 256, 256>>>(ei, ea);
    selfloop_kernel<<<100, 256>>>();
    xcat_kernel<<<(NN * INF_) / 256, 256>>>(x);
    wd_kernel<<<1, 288>>>(We0, ae0, We1, ae1, We2, ae2);

    // layer 0: GAT(400 -> 4x64) + BN + ReLU
    gemm_kernel<<<dim3(4, 400), 256>>>(0, W0, 256, 400);
    attn_kernel<<<NN, 128>>>(4, as0, ad0);
    agg_kernel<4><<<NN / 8, 256>>>(b0, bng, bnb, bnm, bnv, 0, 1, 0);

    // layer 1: GAT(256 -> 4x64) + BN + ReLU
    gemm_kernel<<<dim3(4, 400), 256>>>(1, W1, 256, 256);
    attn_kernel<<<NN, 128>>>(4, as1, ad1);
    agg_kernel<4><<<NN / 8, 256>>>(b1, bng, bnb, bnm, bnv, 4, 1, 0);

    // layer 2: GAT(256 -> 1x64)
    gemm_kernel<<<dim3(1, 400), 256>>>(1, W2, 64, 256);
    attn_kernel<<<NN, 32>>>(1, as2, ad2);
    agg_kernel<1><<<NN / 8, 256>>>(b2, bng, bnb, bnm, bnv, 8, 0, 1);

    // pool + head
    pool_kernel<<<NN, 64>>>(batch);
    head_kernel<<<GG, 64>>>(cw1, cb1, cw2, cb2, out);
}

// round 2
// speedup vs baseline: 1.3060x; 1.3060x over previous
#include <cuda_runtime.h>
#include <math.h>
#include <stdint.h>

// Problem constants
#define NN   25600          // nodes
#define EE   409600         // edges
#define GG   128            // graphs
#define INF_ 200            // raw feature dim
#define IN2  400            // 2*IN after nan-mask concat
#define HC4  256            // H*C for layers 0/1
#define ETOT (EE + NN)      // edges + self loops

// ---------------- scratch (device globals; no allocation allowed) ----------------
__device__ __align__(16) float d_xcat[(size_t)NN * IN2];     // 41 MB
__device__ __align__(16) float d_h   [(size_t)NN * HC4];     // 26 MB  (GEMM output / attn input)
__device__ __align__(16) float d_xn  [(size_t)NN * HC4];     // 26 MB  (next-layer input)
__device__ __align__(16) float d_o2  [(size_t)NN * 64];      // layer-2 node output
__device__ __align__(16) float d_asb[NN * 4];
__device__ __align__(16) float d_adb[NN * 4];
__device__ int   d_cnt[NN];
__device__ int   d_fill[NN];
__device__ float d_easum[NN];
__device__ int   d_rowptr[NN + 1];
__device__ int   d_csrc[ETOT];
__device__ float d_cea [ETOT];
__device__ float d_gsum[GG * 64];
__device__ float d_gcnt[GG];
__device__ float d_wd[9];   // we_dot: layer0 heads 0..3, layer1 heads 4..7, layer2 at 8

// ---------------- helpers ----------------
__device__ __forceinline__ float warp_max(float v) {
    #pragma unroll
    for (int o = 16; o; o >>= 1) v = fmaxf(v, __shfl_xor_sync(0xffffffffu, v, o));
    return v;
}
__device__ __forceinline__ float warp_sum(float v) {
    #pragma unroll
    for (int o = 16; o; o >>= 1) v += __shfl_xor_sync(0xffffffffu, v, o);
    return v;
}
// packed fp32x2 FMA (Blackwell FFMA2 — only reachable via PTX)
__device__ __forceinline__ void ffma2(uint64_t& d, uint64_t a, uint64_t b) {
    asm("fma.rn.f32x2 %0, %1, %2, %0;" : "+l"(d) : "l"(a), "l"(b));
}
__device__ __forceinline__ uint64_t dup2(float v) {
    uint64_t r; asm("mov.b64 %0, {%1, %1};" : "=l"(r) : "f"(v)); return r;
}
__device__ __forceinline__ float2 unpk(uint64_t v) {
    float2 r; asm("mov.b64 {%0, %1}, %2;" : "=f"(r.x), "=f"(r.y) : "l"(v)); return r;
}

// ---------------- zero scratch counters ----------------
__global__ void zero_kernel() {
    int i = blockIdx.x * blockDim.x + threadIdx.x;
    if (i < NN) { d_cnt[i] = 0; d_fill[i] = 0; d_easum[i] = 0.f; }
    if (i < GG * 64) d_gsum[i] = 0.f;
    if (i < GG) d_gcnt[i] = 0.f;
}

// ---------------- CSR build ----------------
__global__ void count_kernel(const int* __restrict__ ei, const float* __restrict__ ea) {
    int e = blockIdx.x * blockDim.x + threadIdx.x;
    if (e >= EE) return;
    int d = ei[EE + e];
    float v = ea[e];
    if (v != v) v = 0.f;              // nan_to_num
    atomicAdd(&d_cnt[d], 1);
    atomicAdd(&d_easum[d], v);
}

// single-block exclusive scan of (cnt[n]+1) -> rowptr, warp-shuffle based
__global__ void scan_kernel() {
    __shared__ int wsum[32];
    __shared__ int s_off;
    int tid = threadIdx.x, lane = tid & 31, wid = tid >> 5;
    if (tid == 0) { d_rowptr[0] = 0; s_off = 0; }
    __syncthreads();
    for (int base = 0; base < NN; base += 1024) {
        int v = d_cnt[base + tid] + 1;    // +1 for the self loop
        int inc = v;
        #pragma unroll
        for (int o = 1; o < 32; o <<= 1) {
            int t = __shfl_up_sync(0xffffffffu, inc, o);
            if (lane >= o) inc += t;
        }
        if (lane == 31) wsum[wid] = inc;
        __syncthreads();
        if (wid == 0) {
            int wi = wsum[lane];
            #pragma unroll
            for (int o = 1; o < 32; o <<= 1) {
                int t = __shfl_up_sync(0xffffffffu, wi, o);
                if (lane >= o) wi += t;
            }
            wsum[lane] = wi;              // inclusive warp sums
        }
        __syncthreads();
        int excl_w = wid ? wsum[wid - 1] : 0;
        d_rowptr[base + tid + 1] = s_off + excl_w + inc;
        __syncthreads();
        if (tid == 0) s_off += wsum[31];
        __syncthreads();
    }
}

__global__ void fill_kernel(const int* __restrict__ ei, const float* __restrict__ ea) {
    int e = blockIdx.x * blockDim.x + threadIdx.x;
    if (e >= EE) return;
    int s = ei[e], d = ei[EE + e];
    float v = ea[e];
    if (v != v) v = 0.f;
    int pos = d_rowptr[d] + atomicAdd(&d_fill[d], 1);
    d_csrc[pos] = s;
    d_cea[pos]  = v;
}

__global__ void selfloop_kernel() {
    int n = blockIdx.x * blockDim.x + threadIdx.x;
    if (n >= NN) return;
    int pos = d_rowptr[n + 1] - 1;    // self loop occupies the last slot of the row
    d_csrc[pos] = n;
    d_cea[pos]  = d_easum[n] / fmaxf((float)d_cnt[n], 1.f);
}

// ---------------- feature prep: [nan_to_num(x), isnan(x)], float4 vectorized ----------------
__global__ void xcat_kernel(const float* __restrict__ x) {
    int i = blockIdx.x * blockDim.x + threadIdx.x;   // < NN*50
    if (i >= NN * (INF_ / 4)) return;
    int n = i / (INF_ / 4), k = i % (INF_ / 4);
    float4 v = ((const float4*)x)[i];
    float4 m;
    m.x = (v.x != v.x) ? 1.f : 0.f; if (v.x != v.x) v.x = 0.f;
    m.y = (v.y != v.y) ? 1.f : 0.f; if (v.y != v.y) v.y = 0.f;
    m.z = (v.z != v.z) ? 1.f : 0.f; if (v.z != v.z) v.z = 0.f;
    m.w = (v.w != v.w) ? 1.f : 0.f; if (v.w != v.w) v.w = 0.f;
    float4* ob = (float4*)(d_xcat + (size_t)n * IN2);
    ob[k]              = v;
    ob[INF_ / 4 + k]   = m;
}

// ---------------- we_dot[h] = dot(We row of head h, ae[h]) ----------------
__global__ void wd_kernel(const float* We0, const float* ae0,
                          const float* We1, const float* ae1,
                          const float* We2, const float* ae2) {
    int w = threadIdx.x >> 5, lane = threadIdx.x & 31;
    if (w >= 9) return;
    const float *We, *ae; int h;
    if (w < 4)      { We = We0; ae = ae0; h = w; }
    else if (w < 8) { We = We1; ae = ae1; h = w - 4; }
    else            { We = We2; ae = ae2; h = 0; }
    float s = 0.f;
    for (int c = lane; c < 64; c += 32) s += We[h * 64 + c] * ae[h * 64 + c];
    s = warp_sum(s);
    if (lane == 0) d_wd[w] = s;
}

// ---------------- f32x2 GEMM: d_h = A @ B, A row-major [25600,K], B [K,Nn] ----------------
// BM x BN block tile, 8x8 per thread (split as 2x2 blocks of 4x4 across the halves),
// 256 threads, double-buffered smem, one __syncthreads per k-tile.
template <int BM, int BN>
__global__ __launch_bounds__(256, 1) void gemm2_kernel(int asel, const float* __restrict__ B,
                                                       int Nn, int K) {
    const float* __restrict__ A = asel ? d_xn : d_xcat;
    constexpr int TX = BN / 8;          // threads across
    constexpr int HM = BM / 2, HN = BN / 2;
    constexpr int AV = BM / 64;         // A float4 loads per thread per tile
    constexpr int BV = BN / 64;         // B float4 loads per thread per tile
    constexpr int BN4 = BN / 4;
    constexpr int BMP = BM + 4;         // pad, keeps 16B alignment of rows

    __shared__ __align__(16) float As[2][16][BMP];
    __shared__ __align__(16) float Bs[2][16][BN];

    int tid = threadIdx.x;
    int tx4 = (tid % TX) * 4;
    int ty4 = (tid / TX) * 4;
    int m0 = blockIdx.y * BM, n0 = blockIdx.x * BN;

    uint64_t acc[4][8];
    #pragma unroll
    for (int i = 0; i < 4; i++)
        #pragma unroll
        for (int j = 0; j < 8; j++) acc[i][j] = 0ull;

    float4 pa[AV], pb[BV];
    int arow[AV], ac[AV], brow[BV], bc[BV];
    #pragma unroll
    for (int i = 0; i < AV; i++) { int idx = tid + i * 256; arow[i] = idx >> 2; ac[i] = idx & 3; }
    #pragma unroll
    for (int i = 0; i < BV; i++) { int idx = tid + i * 256; brow[i] = idx / BN4; bc[i] = idx % BN4; }

    int ktiles = K >> 4;

    // preload tile 0
    #pragma unroll
    for (int i = 0; i < AV; i++)
        pa[i] = *(const float4*)&A[(size_t)(m0 + arow[i]) * K + ac[i] * 4];
    #pragma unroll
    for (int i = 0; i < BV; i++)
        pb[i] = *(const float4*)&B[(size_t)brow[i] * Nn + n0 + bc[i] * 4];
    #pragma unroll
    for (int i = 0; i < AV; i++) {
        As[0][ac[i] * 4 + 0][arow[i]] = pa[i].x;
        As[0][ac[i] * 4 + 1][arow[i]] = pa[i].y;
        As[0][ac[i] * 4 + 2][arow[i]] = pa[i].z;
        As[0][ac[i] * 4 + 3][arow[i]] = pa[i].w;
    }
    #pragma unroll
    for (int i = 0; i < BV; i++)
        *(float4*)&Bs[0][brow[i]][bc[i] * 4] = pb[i];
    __syncthreads();

    for (int t = 0; t < ktiles; t++) {
        int buf = t & 1;
        if (t + 1 < ktiles) {
            int k0 = (t + 1) << 4;
            #pragma unroll
            for (int i = 0; i < AV; i++)
                pa[i] = *(const float4*)&A[(size_t)(m0 + arow[i]) * K + k0 + ac[i] * 4];
            #pragma unroll
            for (int i = 0; i < BV; i++)
                pb[i] = *(const float4*)&B[(size_t)(k0 + brow[i]) * Nn + n0 + bc[i] * 4];
        }
        const float (*Asb)[BMP] = As[buf];
        const float (*Bsb)[BN]  = Bs[buf];
        #pragma unroll
        for (int k = 0; k < 16; k++) {
            ulonglong2 aLo = *(const ulonglong2*)&Asb[k][ty4];
            ulonglong2 aHi = *(const ulonglong2*)&Asb[k][HM + ty4];
            float4 bLo = *(const float4*)&Bsb[k][tx4];
            float4 bHi = *(const float4*)&Bsb[k][HN + tx4];
            uint64_t a2[4] = {aLo.x, aLo.y, aHi.x, aHi.y};
            float bb[8] = {bLo.x, bLo.y, bLo.z, bLo.w, bHi.x, bHi.y, bHi.z, bHi.w};
            #pragma unroll
            for (int j = 0; j < 8; j++) {
                uint64_t bd = dup2(bb[j]);
                #pragma unroll
                for (int ii = 0; ii < 4; ii++) ffma2(acc[ii][j], a2[ii], bd);
            }
        }
        if (t + 1 < ktiles) {
            int nb = buf ^ 1;
            #pragma unroll
            for (int i = 0; i < AV; i++) {
                As[nb][ac[i] * 4 + 0][arow[i]] = pa[i].x;
                As[nb][ac[i] * 4 + 1][arow[i]] = pa[i].y;
                As[nb][ac[i] * 4 + 2][arow[i]] = pa[i].z;
                As[nb][ac[i] * 4 + 3][arow[i]] = pa[i].w;
            }
            #pragma unroll
            for (int i = 0; i < BV; i++)
                *(float4*)&Bs[nb][brow[i]][bc[i] * 4] = pb[i];
        }
        __syncthreads();
    }

    // epilogue: acc[ii][j] .lo/.hi = two consecutive M rows, col j
    #pragma unroll
    for (int ii = 0; ii < 4; ii++) {
        int rbase = (ii < 2) ? (ty4 + ii * 2) : (HM + ty4 + (ii - 2) * 2);
        float2 u[8];
        #pragma unroll
        for (int j = 0; j < 8; j++) u[j] = unpk(acc[ii][j]);
        size_t r0 = (size_t)(m0 + rbase) * Nn;
        size_t r1 = r0 + Nn;
        *(float4*)&d_h[r0 + n0 + tx4]      = make_float4(u[0].x, u[1].x, u[2].x, u[3].x);
        *(float4*)&d_h[r0 + n0 + HN + tx4] = make_float4(u[4].x, u[5].x, u[6].x, u[7].x);
        *(float4*)&d_h[r1 + n0 + tx4]      = make_float4(u[0].y, u[1].y, u[2].y, u[3].y);
        *(float4*)&d_h[r1 + n0 + HN + tx4] = make_float4(u[4].y, u[5].y, u[6].y, u[7].y);
    }
}

// ---------------- per-node attention scalars a_s, a_d ----------------
__global__ void attn_kernel(int Hh, const float* __restrict__ att_s, const float* __restrict__ att_d) {
    int n = blockIdx.x;
    int w = threadIdx.x >> 5, lane = threadIdx.x & 31;
    const float2* hr = (const float2*)(d_h + (size_t)n * Hh * 64 + w * 64);
    const float2* asv = (const float2*)(att_s + w * 64);
    const float2* adv = (const float2*)(att_d + w * 64);
    float2 hv = hr[lane], sv = asv[lane], dv = adv[lane];
    float s  = hv.x * sv.x + hv.y * sv.y;
    float dd = hv.x * dv.x + hv.y * dv.y;
    s = warp_sum(s); dd = warp_sum(dd);
    if (lane == 0) { d_asb[n * Hh + w] = s; d_adb[n * Hh + w] = dd; }
}

// ---------------- segment softmax + aggregation: one warp per dst node ----------------
template <int H>
__global__ void agg_kernel(const float* __restrict__ bias,
                           const float* __restrict__ bng, const float* __restrict__ bnb,
                           const float* __restrict__ bnm, const float* __restrict__ bnv,
                           int wd_off, int do_bn, int out_sel) {
    int gw = (blockIdx.x * blockDim.x + threadIdx.x) >> 5;
    if (gw >= NN) return;
    int lane = threadIdx.x & 31;
    int n = gw;
    int beg = d_rowptr[n], end = d_rowptr[n + 1];

    float adh[H], wdv[H];
    #pragma unroll
    for (int h = 0; h < H; h++) { adh[h] = d_adb[n * H + h]; wdv[h] = d_wd[wd_off + h]; }

    // pass 1: segment max per head
    float mx[H];
    #pragma unroll
    for (int h = 0; h < H; h++) mx[h] = -INFINITY;
    for (int e = beg + lane; e < end; e += 32) {
        int s = d_csrc[e]; float ev = d_cea[e];
        float av[H];
        if constexpr (H == 4) {
            float4 a4 = *(const float4*)&d_asb[s * 4];
            av[0] = a4.x; av[1] = a4.y; av[2] = a4.z; av[3] = a4.w;
        } else {
            av[0] = d_asb[s];
        }
        #pragma unroll
        for (int h = 0; h < H; h++) {
            float t = av[h] + adh[h] + ev * wdv[h];
            t = t > 0.f ? t : 0.2f * t;
            mx[h] = fmaxf(mx[h], t);
        }
    }
    #pragma unroll
    for (int h = 0; h < H; h++) mx[h] = warp_max(mx[h]);

    // pass 2: segment sum of exp
    float sm[H];
    #pragma unroll
    for (int h = 0; h < H; h++) sm[h] = 0.f;
    for (int e = beg + lane; e < end; e += 32) {
        int s = d_csrc[e]; float ev = d_cea[e];
        float av[H];
        if constexpr (H == 4) {
            float4 a4 = *(const float4*)&d_asb[s * 4];
            av[0] = a4.x; av[1] = a4.y; av[2] = a4.z; av[3] = a4.w;
        } else {
            av[0] = d_asb[s];
        }
        #pragma unroll
        for (int h = 0; h < H; h++) {
            float t = av[h] + adh[h] + ev * wdv[h];
            t = t > 0.f ? t : 0.2f * t;
            sm[h] += expf(t - mx[h]);
        }
    }
    #pragma unroll
    for (int h = 0; h < H; h++) sm[h] = warp_sum(sm[h]);

    // pass 3: weighted aggregation; each lane owns PL consecutive channels
    constexpr int PL = (H * 64) / 32;     // 8 (H=4) or 2 (H=1)
    int hl = (lane * PL) >> 6;            // head of this lane's channels
    float adl = adh[hl], wdl = wdv[hl], mxl = mx[hl];
    float invl = 1.f / (sm[hl] + 1e-16f);
    float acc[PL];
    #pragma unroll
    for (int j = 0; j < PL; j++) acc[j] = 0.f;

    for (int e = beg; e < end; e++) {
        int s = d_csrc[e]; float ev = d_cea[e];
        float t = d_asb[s * H + hl] + adl + ev * wdl;
        t = t > 0.f ? t : 0.2f * t;
        float w = expf(t - mxl) * invl;
        const float* hr = d_h + (size_t)s * (H * 64) + lane * PL;
        if constexpr (PL == 8) {
            float4 v0 = *(const float4*)hr;
            float4 v1 = *(const float4*)(hr + 4);
            acc[0] = fmaf(w, v0.x, acc[0]); acc[1] = fmaf(w, v0.y, acc[1]);
            acc[2] = fmaf(w, v0.z, acc[2]); acc[3] = fmaf(w, v0.w, acc[3]);
            acc[4] = fmaf(w, v1.x, acc[4]); acc[5] = fmaf(w, v1.y, acc[5]);
            acc[6] = fmaf(w, v1.z, acc[6]); acc[7] = fmaf(w, v1.w, acc[7]);
        } else {
            float2 v = *(const float2*)hr;
            acc[0] = fmaf(w, v.x, acc[0]);
            acc[1] = fmaf(w, v.y, acc[1]);
        }
    }

    float* ob = out_sel ? d_o2 : d_xn;
    #pragma unroll
    for (int j = 0; j < PL; j++) {
        int c = lane * PL + j;
        float v = acc[j] + bias[c];
        if (do_bn) {
            v = (v - bnm[c]) * rsqrtf(bnv[c] + 1e-5f) * bng[c] + bnb[c];
            v = fmaxf(v, 0.f);
        }
        ob[(size_t)n * (H * 64) + c] = v;
    }
}

// ---------------- global mean pool accumulation ----------------
__global__ void pool_kernel(const int* __restrict__ batch) {
    int n = blockIdx.x; int c = threadIdx.x;   // 64 threads
    int b = batch[n];
    atomicAdd(&d_gsum[b * 64 + c], d_o2[(size_t)n * 64 + c]);
    if (c == 0) atomicAdd(&d_gcnt[b], 1.f);
}

// ---------------- MLP head: GELU(g@cw1+cb1)@cw2+cb2 ----------------
__global__ void head_kernel(const float* __restrict__ cw1, const float* __restrict__ cb1,
                            const float* __restrict__ cw2, const float* __restrict__ cb2,
                            float* __restrict__ out) {
    int g = blockIdx.x, j = threadIdx.x;   // 64 threads
    __shared__ float sg[64], sh[64];
    float cntv = fmaxf(d_gcnt[g], 1.f);
    sg[j] = d_gsum[g * 64 + j] / cntv;
    __syncthreads();
    float a = cb1[j];
    #pragma unroll
    for (int k = 0; k < 64; k++) a = fmaf(sg[k], cw1[k * 64 + j], a);
    sh[j] = 0.5f * a * (1.f + erff(a * 0.70710678118654752440f));   // exact GELU
    __syncthreads();
    if (j < 2) {
        float o = cb2[j];
        #pragma unroll
        for (int k = 0; k < 64; k++) o = fmaf(sh[k], cw2[k * 2 + j], o);
        out[g * 2 + j] = o;
    }
}

// ---------------- launch ----------------
extern "C" void kernel_launch(void* const* d_in, const int* in_sizes, int n_in,
                              void* d_out, int out_size) {
    (void)in_sizes; (void)n_in; (void)out_size;
    const float* x     = (const float*)d_in[0];
    const int*   ei    = (const int*)  d_in[1];
    const float* ea    = (const float*)d_in[2];
    const int*   batch = (const int*)  d_in[3];
    const float* W0  = (const float*)d_in[4];
    const float* as0 = (const float*)d_in[5];
    const float* ad0 = (const float*)d_in[6];
    const float* We0 = (const float*)d_in[7];
    const float* ae0 = (const float*)d_in[8];
    const float* b0  = (const float*)d_in[9];
    const float* W1  = (const float*)d_in[10];
    const float* as1 = (const float*)d_in[11];
    const float* ad1 = (const float*)d_in[12];
    const float* We1 = (const float*)d_in[13];
    const float* ae1 = (const float*)d_in[14];
    const float* b1  = (const float*)d_in[15];
    const float* W2  = (const float*)d_in[16];
    const float* as2 = (const float*)d_in[17];
    const float* ad2 = (const float*)d_in[18];
    const float* We2 = (const float*)d_in[19];
    const float* ae2 = (const float*)d_in[20];
    const float* b2  = (const float*)d_in[21];
    const float* bng = (const float*)d_in[22];
    const float* bnb = (const float*)d_in[23];
    const float* bnm = (const float*)d_in[24];
    const float* bnv = (const float*)d_in[25];
    const float* cw1 = (const float*)d_in[26];
    const float* cb1 = (const float*)d_in[27];
    const float* cw2 = (const float*)d_in[28];
    const float* cb2 = (const float*)d_in[29];
    float* out = (float*)d_out;

    // graph prep (identical across layers)
    zero_kernel<<<100, 256>>>();
    count_kernel<<<EE / 256, 256>>>(ei, ea);
    scan_kernel<<<1, 1024>>>();
    fill_kernel<<<EE / 256, 256>>>(ei, ea);
    selfloop_kernel<<<100, 256>>>();
    xcat_kernel<<<(NN * (INF_ / 4) + 255) / 256, 256>>>(x);
    wd_kernel<<<1, 288>>>(We0, ae0, We1, ae1, We2, ae2);

    // layer 0: GAT(400 -> 4x64) + BN + ReLU
    gemm2_kernel<128, 128><<<dim3(2, 200), 256>>>(0, W0, 256, 400);
    attn_kernel<<<NN, 128>>>(4, as0, ad0);
    agg_kernel<4><<<NN / 8, 256>>>(b0, bng, bnb, bnm, bnv, 0, 1, 0);

    // layer 1: GAT(256 -> 4x64) + BN + ReLU
    gemm2_kernel<128, 128><<<dim3(2, 200), 256>>>(1, W1, 256, 256);
    attn_kernel<<<NN, 128>>>(4, as1, ad1);
    agg_kernel<4><<<NN / 8, 256>>>(b1, bng, bnb, bnm, bnv, 4, 1, 0);

    // layer 2: GAT(256 -> 1x64)
    gemm2_kernel<256, 64><<<dim3(1, 100), 256>>>(1, W2, 64, 256);
    attn_kernel<<<NN, 32>>>(1, as2, ad2);
    agg_kernel<1><<<NN / 8, 256>>>(b2, bng, bnb, bnm, bnv, 8, 0, 1);

    // pool + head
    pool_kernel<<<NN, 64>>>(batch);
    head_kernel<<<GG, 64>>>(cw1, cb1, cw2, cb2, out);
}

// round 3
// speedup vs baseline: 1.4625x; 1.1199x over previous
#include <cuda_runtime.h>
#include <math.h>
#include <stdint.h>

// Problem constants
#define NN   25600          // nodes
#define EE   409600         // edges
#define GG   128            // graphs
#define INF_ 200            // raw feature dim
#define IN2  400            // 2*IN after nan-mask concat
#define HC4  256            // H*C for layers 0/1
#define ETOT (EE + NN)      // edges + self loops

// ---------------- scratch (device globals; no allocation allowed) ----------------
__device__ __align__(16) float d_h   [(size_t)NN * HC4];     // 26 MB  (GEMM output / attn input)
__device__ __align__(16) float d_xn  [(size_t)NN * HC4];     // 26 MB  (next-layer input)
__device__ __align__(16) float d_o2  [(size_t)NN * 64];      // layer-2 node output
__device__ __align__(16) float d_asb[NN * 4];
__device__ __align__(16) float d_adb[NN * 4];
__device__ int   d_cnt[NN];
__device__ int   d_fill[NN];
__device__ float d_easum[NN];
__device__ int   d_rowptr[NN + 1];
__device__ int   d_csrc[ETOT];
__device__ float d_cea [ETOT];
__device__ float d_gsum[GG * 64];
__device__ float d_gcnt[GG];
__device__ float d_wd[9];   // we_dot: layer0 heads 0..3, layer1 heads 4..7, layer2 at 8

// ---------------- helpers ----------------
__device__ __forceinline__ float warp_max(float v) {
    #pragma unroll
    for (int o = 16; o; o >>= 1) v = fmaxf(v, __shfl_xor_sync(0xffffffffu, v, o));
    return v;
}
__device__ __forceinline__ float warp_sum(float v) {
    #pragma unroll
    for (int o = 16; o; o >>= 1) v += __shfl_xor_sync(0xffffffffu, v, o);
    return v;
}
// packed fp32x2 FMA (Blackwell FFMA2 — only reachable via PTX)
__device__ __forceinline__ void ffma2(uint64_t& d, uint64_t a, uint64_t b) {
    asm("fma.rn.f32x2 %0, %1, %2, %0;" : "+l"(d) : "l"(a), "l"(b));
}
__device__ __forceinline__ uint64_t dup2(float v) {
    uint64_t r; asm("mov.b64 %0, {%1, %1};" : "=l"(r) : "f"(v)); return r;
}
__device__ __forceinline__ float2 unpk(uint64_t v) {
    float2 r; asm("mov.b64 {%0, %1}, %2;" : "=f"(r.x), "=f"(r.y) : "l"(v)); return r;
}

// ---------------- zero scratch counters ----------------
__global__ void zero_kernel() {
    int i = blockIdx.x * blockDim.x + threadIdx.x;
    if (i < NN) { d_cnt[i] = 0; d_fill[i] = 0; d_easum[i] = 0.f; }
    if (i < GG * 64) d_gsum[i] = 0.f;
    if (i < GG) d_gcnt[i] = 0.f;
}

// ---------------- CSR build ----------------
__global__ void count_kernel(const int* __restrict__ ei, const float* __restrict__ ea) {
    int e = blockIdx.x * blockDim.x + threadIdx.x;
    if (e >= EE) return;
    int d = ei[EE + e];
    float v = ea[e];
    if (v != v) v = 0.f;              // nan_to_num
    atomicAdd(&d_cnt[d], 1);
    atomicAdd(&d_easum[d], v);
}

// single-block exclusive scan of (cnt[n]+1) -> rowptr, warp-shuffle based
__global__ void scan_kernel() {
    __shared__ int wsum[32];
    __shared__ int s_off;
    int tid = threadIdx.x, lane = tid & 31, wid = tid >> 5;
    if (tid == 0) { d_rowptr[0] = 0; s_off = 0; }
    __syncthreads();
    for (int base = 0; base < NN; base += 1024) {
        int v = d_cnt[base + tid] + 1;    // +1 for the self loop
        int inc = v;
        #pragma unroll
        for (int o = 1; o < 32; o <<= 1) {
            int t = __shfl_up_sync(0xffffffffu, inc, o);
            if (lane >= o) inc += t;
        }
        if (lane == 31) wsum[wid] = inc;
        __syncthreads();
        if (wid == 0) {
            int wi = wsum[lane];
            #pragma unroll
            for (int o = 1; o < 32; o <<= 1) {
                int t = __shfl_up_sync(0xffffffffu, wi, o);
                if (lane >= o) wi += t;
            }
            wsum[lane] = wi;              // inclusive warp sums
        }
        __syncthreads();
        int excl_w = wid ? wsum[wid - 1] : 0;
        d_rowptr[base + tid + 1] = s_off + excl_w + inc;
        __syncthreads();
        if (tid == 0) s_off += wsum[31];
        __syncthreads();
    }
}

__global__ void fill_kernel(const int* __restrict__ ei, const float* __restrict__ ea) {
    int e = blockIdx.x * blockDim.x + threadIdx.x;
    if (e >= EE) return;
    int s = ei[e], d = ei[EE + e];
    float v = ea[e];
    if (v != v) v = 0.f;
    int pos = d_rowptr[d] + atomicAdd(&d_fill[d], 1);
    d_csrc[pos] = s;
    d_cea[pos]  = v;
}

__global__ void selfloop_kernel() {
    int n = blockIdx.x * blockDim.x + threadIdx.x;
    if (n >= NN) return;
    int pos = d_rowptr[n + 1] - 1;    // self loop occupies the last slot of the row
    d_csrc[pos] = n;
    d_cea[pos]  = d_easum[n] / fmaxf((float)d_cnt[n], 1.f);
}

// ---------------- we_dot[h] = dot(We row of head h, ae[h]) ----------------
__global__ void wd_kernel(const float* We0, const float* ae0,
                          const float* We1, const float* ae1,
                          const float* We2, const float* ae2) {
    int w = threadIdx.x >> 5, lane = threadIdx.x & 31;
    if (w >= 9) return;
    const float *We, *ae; int h;
    if (w < 4)      { We = We0; ae = ae0; h = w; }
    else if (w < 8) { We = We1; ae = ae1; h = w - 4; }
    else            { We = We2; ae = ae2; h = 0; }
    float s = 0.f;
    for (int c = lane; c < 64; c += 32) s += We[h * 64 + c] * ae[h * 64 + c];
    s = warp_sum(s);
    if (lane == 0) d_wd[w] = s;
}

// ---------------- f32x2 GEMM: d_h = A @ B, A row-major [25600,K], B [K,Nn] ----------------
// XF=1: A is synthesized from raw x: A[m,k] = k<200 ? nan2num(x[m,k]) : isnan(x[m,k-200]).
// BM x BN block tile, 8x8 per thread (2x2 blocks of 4x4 across halves),
// 256 threads, double-buffered smem, one __syncthreads per k-tile.
template <int BM, int BN, int XF, int OCC>
__global__ __launch_bounds__(256, OCC) void gemm2_kernel(const float* __restrict__ Xin,
                                                         const float* __restrict__ B,
                                                         int Nn, int K) {
    const float* __restrict__ A = d_xn;
    constexpr int TX = BN / 8;          // threads across
    constexpr int HM = BM / 2, HN = BN / 2;
    constexpr int AV = BM / 64;         // A float4 loads per thread per tile
    constexpr int BV = BN / 64;         // B float4 loads per thread per tile
    constexpr int BN4 = BN / 4;
    constexpr int BMP = BM + 4;         // pad, keeps 16B alignment of rows

    __shared__ __align__(16) float As[2][16][BMP];
    __shared__ __align__(16) float Bs[2][16][BN];

    int tid = threadIdx.x;
    int tx4 = (tid % TX) * 4;
    int ty4 = (tid / TX) * 4;
    int m0 = blockIdx.y * BM, n0 = blockIdx.x * BN;

    uint64_t acc[4][8];
    #pragma unroll
    for (int i = 0; i < 4; i++)
        #pragma unroll
        for (int j = 0; j < 8; j++) acc[i][j] = 0ull;

    float4 pa[AV], pb[BV];
    int arow[AV], ac[AV], brow[BV], bc[BV];
    #pragma unroll
    for (int i = 0; i < AV; i++) { int idx = tid + i * 256; arow[i] = idx >> 2; ac[i] = idx & 3; }
    #pragma unroll
    for (int i = 0; i < BV; i++) { int idx = tid + i * 256; brow[i] = idx / BN4; bc[i] = idx % BN4; }

    int ktiles = K >> 4;

    // A tile load (handles the fused nan/concat transform when XF=1)
    auto loadA = [&](int i, int k0) -> float4 {
        int m = m0 + arow[i];
        int kk = k0 + ac[i] * 4;
        if (XF) {
            int c = (kk < INF_) ? kk : (kk - INF_);
            float4 v = *(const float4*)&Xin[(size_t)m * INF_ + c];
            float4 r;
            bool lo = (kk < INF_);
            r.x = (v.x != v.x) ? (lo ? 0.f : 1.f) : (lo ? v.x : 0.f);
            r.y = (v.y != v.y) ? (lo ? 0.f : 1.f) : (lo ? v.y : 0.f);
            r.z = (v.z != v.z) ? (lo ? 0.f : 1.f) : (lo ? v.z : 0.f);
            r.w = (v.w != v.w) ? (lo ? 0.f : 1.f) : (lo ? v.w : 0.f);
            return r;
        } else {
            return *(const float4*)&A[(size_t)m * K + kk];
        }
    };

    // preload tile 0
    #pragma unroll
    for (int i = 0; i < AV; i++) pa[i] = loadA(i, 0);
    #pragma unroll
    for (int i = 0; i < BV; i++)
        pb[i] = *(const float4*)&B[(size_t)brow[i] * Nn + n0 + bc[i] * 4];
    #pragma unroll
    for (int i = 0; i < AV; i++) {
        As[0][ac[i] * 4 + 0][arow[i]] = pa[i].x;
        As[0][ac[i] * 4 + 1][arow[i]] = pa[i].y;
        As[0][ac[i] * 4 + 2][arow[i]] = pa[i].z;
        As[0][ac[i] * 4 + 3][arow[i]] = pa[i].w;
    }
    #pragma unroll
    for (int i = 0; i < BV; i++)
        *(float4*)&Bs[0][brow[i]][bc[i] * 4] = pb[i];
    __syncthreads();

    for (int t = 0; t < ktiles; t++) {
        int buf = t & 1;
        if (t + 1 < ktiles) {
            int k0 = (t + 1) << 4;
            #pragma unroll
            for (int i = 0; i < AV; i++) pa[i] = loadA(i, k0);
            #pragma unroll
            for (int i = 0; i < BV; i++)
                pb[i] = *(const float4*)&B[(size_t)(k0 + brow[i]) * Nn + n0 + bc[i] * 4];
        }
        const float (*Asb)[BMP] = As[buf];
        const float (*Bsb)[BN]  = Bs[buf];
        #pragma unroll
        for (int k = 0; k < 16; k++) {
            ulonglong2 aLo = *(const ulonglong2*)&Asb[k][ty4];
            ulonglong2 aHi = *(const ulonglong2*)&Asb[k][HM + ty4];
            float4 bLo = *(const float4*)&Bsb[k][tx4];
            float4 bHi = *(const float4*)&Bsb[k][HN + tx4];
            uint64_t a2[4] = {aLo.x, aLo.y, aHi.x, aHi.y};
            float bb[8] = {bLo.x, bLo.y, bLo.z, bLo.w, bHi.x, bHi.y, bHi.z, bHi.w};
            #pragma unroll
            for (int j = 0; j < 8; j++) {
                uint64_t bd = dup2(bb[j]);
                #pragma unroll
                for (int ii = 0; ii < 4; ii++) ffma2(acc[ii][j], a2[ii], bd);
            }
        }
        if (t + 1 < ktiles) {
            int nb = buf ^ 1;
            #pragma unroll
            for (int i = 0; i < AV; i++) {
                As[nb][ac[i] * 4 + 0][arow[i]] = pa[i].x;
                As[nb][ac[i] * 4 + 1][arow[i]] = pa[i].y;
                As[nb][ac[i] * 4 + 2][arow[i]] = pa[i].z;
                As[nb][ac[i] * 4 + 3][arow[i]] = pa[i].w;
            }
            #pragma unroll
            for (int i = 0; i < BV; i++)
                *(float4*)&Bs[nb][brow[i]][bc[i] * 4] = pb[i];
        }
        __syncthreads();
    }

    // epilogue: acc[ii][j] .lo/.hi = two consecutive M rows, col j
    #pragma unroll
    for (int ii = 0; ii < 4; ii++) {
        int rbase = (ii < 2) ? (ty4 + ii * 2) : (HM + ty4 + (ii - 2) * 2);
        float2 u[8];
        #pragma unroll
        for (int j = 0; j < 8; j++) u[j] = unpk(acc[ii][j]);
        size_t r0 = (size_t)(m0 + rbase) * Nn;
        size_t r1 = r0 + Nn;
        *(float4*)&d_h[r0 + n0 + tx4]      = make_float4(u[0].x, u[1].x, u[2].x, u[3].x);
        *(float4*)&d_h[r0 + n0 + HN + tx4] = make_float4(u[4].x, u[5].x, u[6].x, u[7].x);
        *(float4*)&d_h[r1 + n0 + tx4]      = make_float4(u[0].y, u[1].y, u[2].y, u[3].y);
        *(float4*)&d_h[r1 + n0 + HN + tx4] = make_float4(u[4].y, u[5].y, u[6].y, u[7].y);
    }
}

// ---------------- per-node attention scalars a_s, a_d ----------------
__global__ void attn_kernel(int Hh, const float* __restrict__ att_s, const float* __restrict__ att_d) {
    int n = blockIdx.x;
    int w = threadIdx.x >> 5, lane = threadIdx.x & 31;
    const float2* hr = (const float2*)(d_h + (size_t)n * Hh * 64 + w * 64);
    const float2* asv = (const float2*)(att_s + w * 64);
    const float2* adv = (const float2*)(att_d + w * 64);
    float2 hv = hr[lane], sv = asv[lane], dv = adv[lane];
    float s  = hv.x * sv.x + hv.y * sv.y;
    float dd = hv.x * dv.x + hv.y * dv.y;
    s = warp_sum(s); dd = warp_sum(dd);
    if (lane == 0) { d_asb[n * Hh + w] = s; d_adb[n * Hh + w] = dd; }
}

// ---------------- segment softmax + aggregation: one warp per dst node ----------------
template <int H>
__global__ __launch_bounds__(256) void agg_kernel(const float* __restrict__ bias,
                           const float* __restrict__ bng, const float* __restrict__ bnb,
                           const float* __restrict__ bnm, const float* __restrict__ bnv,
                           int wd_off, int do_bn, int out_sel) {
    __shared__ int   s_src[8][32];
    __shared__ float s_wt[8][32][H];

    int gw = (blockIdx.x * blockDim.x + threadIdx.x) >> 5;
    if (gw >= NN) return;
    int lane = threadIdx.x & 31;
    int wwarp = threadIdx.x >> 5;
    int n = gw;
    int beg = d_rowptr[n], end = d_rowptr[n + 1];

    float adh[H], wdv[H];
    #pragma unroll
    for (int h = 0; h < H; h++) { adh[h] = d_adb[n * H + h]; wdv[h] = d_wd[wd_off + h]; }

    // pass 1: segment max per head (lane-strided)
    float mx[H];
    #pragma unroll
    for (int h = 0; h < H; h++) mx[h] = -INFINITY;
    for (int e = beg + lane; e < end; e += 32) {
        int s = d_csrc[e]; float ev = d_cea[e];
        float av[H];
        if constexpr (H == 4) {
            float4 a4 = *(const float4*)&d_asb[s * 4];
            av[0] = a4.x; av[1] = a4.y; av[2] = a4.z; av[3] = a4.w;
        } else {
            av[0] = d_asb[s];
        }
        #pragma unroll
        for (int h = 0; h < H; h++) {
            float t = av[h] + adh[h] + ev * wdv[h];
            t = t > 0.f ? t : 0.2f * t;
            mx[h] = fmaxf(mx[h], t);
        }
    }
    #pragma unroll
    for (int h = 0; h < H; h++) mx[h] = warp_max(mx[h]);

    // pass 2: segment sum of exp (lane-strided)
    float sm[H];
    #pragma unroll
    for (int h = 0; h < H; h++) sm[h] = 0.f;
    for (int e = beg + lane; e < end; e += 32) {
        int s = d_csrc[e]; float ev = d_cea[e];
        float av[H];
        if constexpr (H == 4) {
            float4 a4 = *(const float4*)&d_asb[s * 4];
            av[0] = a4.x; av[1] = a4.y; av[2] = a4.z; av[3] = a4.w;
        } else {
            av[0] = d_asb[s];
        }
        #pragma unroll
        for (int h = 0; h < H; h++) {
            float t = av[h] + adh[h] + ev * wdv[h];
            t = t > 0.f ? t : 0.2f * t;
            sm[h] += expf(t - mx[h]);
        }
    }
    #pragma unroll
    for (int h = 0; h < H; h++) sm[h] = warp_sum(sm[h]);

    // pass 3: chunked weighted aggregation; each lane owns PL consecutive channels.
    // Weights computed lane-parallel per 32-edge chunk into smem, gathers are
    // independent and software-pipelineable. Normalization hoisted out.
    constexpr int PL = (H * 64) / 32;     // 8 (H=4) or 2 (H=1)
    int hl = (lane * PL) >> 6;            // head of this lane's channels
    float acc[PL];
    #pragma unroll
    for (int j = 0; j < PL; j++) acc[j] = 0.f;

    for (int ec = beg; ec < end; ec += 32) {
        int e = ec + lane;
        if (e < end) {
            int s = d_csrc[e]; float ev = d_cea[e];
            s_src[wwarp][lane] = s;
            float av[H];
            if constexpr (H == 4) {
                float4 a4 = *(const float4*)&d_asb[s * 4];
                av[0] = a4.x; av[1] = a4.y; av[2] = a4.z; av[3] = a4.w;
            } else {
                av[0] = d_asb[s];
            }
            #pragma unroll
            for (int h = 0; h < H; h++) {
                float t = av[h] + adh[h] + ev * wdv[h];
                t = t > 0.f ? t : 0.2f * t;
                s_wt[wwarp][lane][h] = expf(t - mx[h]);
            }
        }
        __syncwarp();
        int cnt = min(32, end - ec);
        #pragma unroll 4
        for (int i = 0; i < cnt; i++) {
            int s = s_src[wwarp][i];
            float w = s_wt[wwarp][i][hl];
            const float* hr = d_h + (size_t)s * (H * 64) + lane * PL;
            if constexpr (PL == 8) {
                float4 v0 = *(const float4*)hr;
                float4 v1 = *(const float4*)(hr + 4);
                acc[0] = fmaf(w, v0.x, acc[0]); acc[1] = fmaf(w, v0.y, acc[1]);
                acc[2] = fmaf(w, v0.z, acc[2]); acc[3] = fmaf(w, v0.w, acc[3]);
                acc[4] = fmaf(w, v1.x, acc[4]); acc[5] = fmaf(w, v1.y, acc[5]);
                acc[6] = fmaf(w, v1.z, acc[6]); acc[7] = fmaf(w, v1.w, acc[7]);
            } else {
                float2 v = *(const float2*)hr;
                acc[0] = fmaf(w, v.x, acc[0]);
                acc[1] = fmaf(w, v.y, acc[1]);
            }
        }
        __syncwarp();
    }

    float invl = 1.f / (sm[hl] + 1e-16f);
    float* ob = out_sel ? d_o2 : d_xn;
    #pragma unroll
    for (int j = 0; j < PL; j++) {
        int c = lane * PL + j;
        float v = acc[j] * invl + bias[c];
        if (do_bn) {
            v = (v - bnm[c]) * rsqrtf(bnv[c] + 1e-5f) * bng[c] + bnb[c];
            v = fmaxf(v, 0.f);
        }
        ob[(size_t)n * (H * 64) + c] = v;
    }
}

// ---------------- global mean pool accumulation ----------------
__global__ void pool_kernel(const int* __restrict__ batch) {
    int n = blockIdx.x; int c = threadIdx.x;   // 64 threads
    int b = batch[n];
    atomicAdd(&d_gsum[b * 64 + c], d_o2[(size_t)n * 64 + c]);
    if (c == 0) atomicAdd(&d_gcnt[b], 1.f);
}

// ---------------- MLP head: GELU(g@cw1+cb1)@cw2+cb2 ----------------
__global__ void head_kernel(const float* __restrict__ cw1, const float* __restrict__ cb1,
                            const float* __restrict__ cw2, const float* __restrict__ cb2,
                            float* __restrict__ out) {
    int g = blockIdx.x, j = threadIdx.x;   // 64 threads
    __shared__ float sg[64], sh[64];
    float cntv = fmaxf(d_gcnt[g], 1.f);
    sg[j] = d_gsum[g * 64 + j] / cntv;
    __syncthreads();
    float a = cb1[j];
    #pragma unroll
    for (int k = 0; k < 64; k++) a = fmaf(sg[k], cw1[k * 64 + j], a);
    sh[j] = 0.5f * a * (1.f + erff(a * 0.70710678118654752440f));   // exact GELU
    __syncthreads();
    if (j < 2) {
        float o = cb2[j];
        #pragma unroll
        for (int k = 0; k < 64; k++) o = fmaf(sh[k], cw2[k * 2 + j], o);
        out[g * 2 + j] = o;
    }
}

// ---------------- launch ----------------
extern "C" void kernel_launch(void* const* d_in, const int* in_sizes, int n_in,
                              void* d_out, int out_size) {
    (void)in_sizes; (void)n_in; (void)out_size;
    const float* x     = (const float*)d_in[0];
    const int*   ei    = (const int*)  d_in[1];
    const float* ea    = (const float*)d_in[2];
    const int*   batch = (const int*)  d_in[3];
    const float* W0  = (const float*)d_in[4];
    const float* as0 = (const float*)d_in[5];
    const float* ad0 = (const float*)d_in[6];
    const float* We0 = (const float*)d_in[7];
    const float* ae0 = (const float*)d_in[8];
    const float* b0  = (const float*)d_in[9];
    const float* W1  = (const float*)d_in[10];
    const float* as1 = (const float*)d_in[11];
    const float* ad1 = (const float*)d_in[12];
    const float* We1 = (const float*)d_in[13];
    const float* ae1 = (const float*)d_in[14];
    const float* b1  = (const float*)d_in[15];
    const float* W2  = (const float*)d_in[16];
    const float* as2 = (const float*)d_in[17];
    const float* ad2 = (const float*)d_in[18];
    const float* We2 = (const float*)d_in[19];
    const float* ae2 = (const float*)d_in[20];
    const float* b2  = (const float*)d_in[21];
    const float* bng = (const float*)d_in[22];
    const float* bnb = (const float*)d_in[23];
    const float* bnm = (const float*)d_in[24];
    const float* bnv = (const float*)d_in[25];
    const float* cw1 = (const float*)d_in[26];
    const float* cb1 = (const float*)d_in[27];
    const float* cw2 = (const float*)d_in[28];
    const float* cb2 = (const float*)d_in[29];
    float* out = (float*)d_out;

    // prep + layer-0 GEMM placed 4th so the ncu window (-s 5 -c 1) lands on it
    zero_kernel<<<100, 256>>>();
    count_kernel<<<EE / 256, 256>>>(ei, ea);
    scan_kernel<<<1, 1024>>>();
    gemm2_kernel<128, 128, 1, 2><<<dim3(2, 200), 256>>>(x, W0, 256, 400);   // layer 0 GEMM (fused nan-concat)
    fill_kernel<<<EE / 256, 256>>>(ei, ea);
    selfloop_kernel<<<100, 256>>>();
    wd_kernel<<<1, 288>>>(We0, ae0, We1, ae1, We2, ae2);

    // layer 0: attention + aggregation + BN + ReLU
    attn_kernel<<<NN, 128>>>(4, as0, ad0);
    agg_kernel<4><<<NN / 8, 256>>>(b0, bng, bnb, bnm, bnv, 0, 1, 0);

    // layer 1: GAT(256 -> 4x64) + BN + ReLU
    gemm2_kernel<128, 128, 0, 2><<<dim3(2, 200), 256>>>(nullptr, W1, 256, 256);
    attn_kernel<<<NN, 128>>>(4, as1, ad1);
    agg_kernel<4><<<NN / 8, 256>>>(b1, bng, bnb, bnm, bnv, 4, 1, 0);

    // layer 2: GAT(256 -> 1x64)
    gemm2_kernel<256, 64, 0, 1><<<dim3(1, 100), 256>>>(nullptr, W2, 64, 256);
    attn_kernel<<<NN, 32>>>(1, as2, ad2);
    agg_kernel<1><<<NN / 8, 256>>>(b2, bng, bnb, bnm, bnv, 8, 0, 1);

    // pool + head
    pool_kernel<<<NN, 64>>>(batch);
    head_kernel<<<GG, 64>>>(cw1, cb1, cw2, cb2, out);
}